// round 12
// baseline (speedup 1.0000x reference)
#include <cuda_runtime.h>
#include <math.h>

// Problem constants (fixed by setup_inputs)
#define B_  32
#define K_  16
#define T_  30
#define N_  128
#define n_  20
#define NN  (N_ * n_)          // 2560 nodes per batch
#define BK  (B_ * K_)          // 512
#define TASKS (BK * T_)        // 15360 warps, one per (bk, t)
#define GRID  (TASKS / 8)      // 1920 blocks x 8 warps
#define BLOCK 256

#define YAW_THRESH  1.0471975511965976f   // pi/3
#define INF_F       __int_as_float(0x7f800000)

// Global scratch (static, zero-init; counters self-reset -> graph-replay safe)
__device__ float g_partial[BK * 32];   // [bk][t]
__device__ int   g_cnt[BK];

__device__ __forceinline__ float fast_sqrt(float x) {
    float r;
    asm("sqrt.approx.f32 %0, %1;" : "=f"(r) : "f"(x));
    return r;
}

// cost = relu(dist - 2) + relu(|wrap(yaw_n - yaw_p)| - pi/3); masked -> inf
// (reference: dist = inf for masked, yaw term finite -> total inf).
// yaw = -atan2(dx, dy) reflects the direction angle, so |wrapped yaw diff| ==
// angle(u, v) between raw direction vectors (starts / t = 0 -> dir (0, 1)).
// Exact-zero (no transcendentals): d2 <= 4 AND dot >= 0 AND cross^2 <= 3*dot^2
// (tan(pi/3)^2 == 3); cost >= 0, so any zero finalizes the min at 0.

// Slow path (P ~ 1e-3 per task): full scan of all NN nodes with running min
// and per-chunk zero early-exit. Returns the warp-reduced min on all lanes.
__device__ __noinline__ float full_scan(const float4* __restrict__ cn4,
                                        const int2*   __restrict__ mk2,
                                        const float2* __restrict__ cnb,
                                        float2 pt, float vx, float vy,
                                        int lane) {
    float lmin = INF_F;
    for (int r = 0; r < NN / 64; ++r) {
        float4 v = cn4[r * 32 + lane];
        int2   m = mk2[r * 32 + lane];
        float px = __shfl_up_sync(0xffffffffu, v.z, 1);
        float py = __shfl_up_sync(0xffffffffu, v.w, 1);
        if (lane == 0 && r > 0) {
            float2 qq = cnb[r * 64 - 1];
            px = qq.x; py = qq.y;
        }
        // starts: (64r + 2l) % 20 == 0  <=>  l % 10 == (10 - (2r) % 10) % 10
        const int startlane = (10 - (2 * r) % 10) % 10;
        const bool s0 = (lane % 10) == startlane;   // even node; odd never

        float cc[2];
        bool  zz[2];
        {   // node 0 (x, y), prev = (px, py)
            float ux = s0 ? 0.0f : v.x - px;
            float uy = s0 ? 1.0f : v.y - py;
            float xx = (m.x == 1) ? INF_F : v.x;
            float dx = xx - pt.x, dy = v.y - pt.y;
            float d2 = fmaf(dx, dx, dy * dy);
            float dt = fmaf(ux, vx, uy * vy);
            float cr = fmaf(ux, vy, -uy * vx);
            zz[0] = (d2 <= 4.0f) && (dt >= 0.0f) && (cr * cr <= 3.0f * dt * dt);
            float cd = (d2 <= 4.0f) ? 0.0f : (fast_sqrt(d2) - 2.0f);
            float a  = atan2f(fabsf(cr), dt);
            cc[0] = cd + fmaxf(a - YAW_THRESH, 0.0f);
        }
        {   // node 1 (z, w), prev = (x, y), never a start
            float ux = v.z - v.x;
            float uy = v.w - v.y;
            float xx = (m.y == 1) ? INF_F : v.z;
            float dx = xx - pt.x, dy = v.w - pt.y;
            float d2 = fmaf(dx, dx, dy * dy);
            float dt = fmaf(ux, vx, uy * vy);
            float cr = fmaf(ux, vy, -uy * vx);
            zz[1] = (d2 <= 4.0f) && (dt >= 0.0f) && (cr * cr <= 3.0f * dt * dt);
            float cd = (d2 <= 4.0f) ? 0.0f : (fast_sqrt(d2) - 2.0f);
            float a  = atan2f(fabsf(cr), dt);
            cc[1] = cd + fmaxf(a - YAW_THRESH, 0.0f);
        }
        if (__ballot_sync(0xffffffffu, zz[0] | zz[1])) return 0.0f;
        lmin = fminf(lmin, fminf(cc[0], cc[1]));
    }
    lmin = fminf(lmin, __shfl_xor_sync(0xffffffffu, lmin, 16));
    lmin = fminf(lmin, __shfl_xor_sync(0xffffffffu, lmin, 8));
    lmin = fminf(lmin, __shfl_xor_sync(0xffffffffu, lmin, 4));
    lmin = fminf(lmin, __shfl_xor_sync(0xffffffffu, lmin, 2));
    lmin = fminf(lmin, __shfl_xor_sync(0xffffffffu, lmin, 1));
    return lmin;
}

// One warp per (bk, t) task. Fast path: zero-test the first 64 nodes
// (2 per lane, one LDG.128 + one LDG.64) -> ballot -> done (~99.9%).
// Result delivery: per-bk arrival counter; the 30th warp sums the 30
// partials in fixed lane order (deterministic) and writes out[bk].
__global__ __launch_bounds__(BLOCK)
void consistency_kernel(const float* __restrict__ preds,
                        const float* __restrict__ cn,
                        const int*   __restrict__ mask,
                        float* __restrict__ out) {
    const int tid  = threadIdx.x;
    const int lane = tid & 31;
    const int task = blockIdx.x * (BLOCK / 32) + (tid >> 5);
    const int bk   = task / T_;
    const int t    = task - bk * T_;
    const int b    = bk >> 4;              // / K_

    const float2* pp  = (const float2*)preds + (size_t)bk * T_;
    const float4* cn4 = (const float4*)cn + (size_t)b * (NN / 2);
    const int2*   mk2 = (const int2*)mask + (size_t)b * (NN / 2);
    const float2* cnb = (const float2*)cn + (size_t)b * NN;

    const float2 pt = pp[t];
    float vx = 0.0f, vy = 1.0f;            // yaw 0 <-> direction (0, 1)
    if (t != 0) {
        float2 pm = pp[t - 1];
        vx = pt.x - pm.x;
        vy = pt.y - pm.y;
    }

    // ---- fast path: zero-test nodes 0..63 ----
    float4 v = cn4[lane];                  // nodes {2*lane, 2*lane+1}
    int2   m = mk2[lane];
    float px = __shfl_up_sync(0xffffffffu, v.z, 1);  // prev of node 2*lane
    float py = __shfl_up_sync(0xffffffffu, v.w, 1);
    const bool s0 = (lane % 10) == 0;      // starts among 0..63: 0,20,40,60

    bool z0, z1;
    float d2a, dta, cra, d2b, dtb, crb;
    {
        float ux = s0 ? 0.0f : v.x - px;
        float uy = s0 ? 1.0f : v.y - py;
        float xx = (m.x == 1) ? INF_F : v.x;
        float dx = xx - pt.x, dy = v.y - pt.y;
        d2a = fmaf(dx, dx, dy * dy);
        dta = fmaf(ux, vx, uy * vy);
        cra = fmaf(ux, vy, -uy * vx);
        z0 = (d2a <= 4.0f) && (dta >= 0.0f) && (cra * cra <= 3.0f * dta * dta);
    }
    {
        float ux = v.z - v.x;
        float uy = v.w - v.y;
        float xx = (m.y == 1) ? INF_F : v.z;
        float dx = xx - pt.x, dy = v.w - pt.y;
        d2b = fmaf(dx, dx, dy * dy);
        dtb = fmaf(ux, vx, uy * vy);
        crb = fmaf(ux, vy, -uy * vx);
        z1 = (d2b <= 4.0f) && (dtb >= 0.0f) && (crb * crb <= 3.0f * dtb * dtb);
    }

    float res;
    if (__ballot_sync(0xffffffffu, z0 | z1)) {
        res = 0.0f;                        // cost >= 0 -> min finalized
    } else {
        res = full_scan(cn4, mk2, cnb, pt, vx, vy, lane);
    }

    // ---- delivery: store partial, last-arriving warp reduces ----
    if (lane == 0) g_partial[bk * 32 + t] = res;
    __threadfence();
    int old = 0;
    if (lane == 0) old = atomicAdd(&g_cnt[bk], 1);
    old = __shfl_sync(0xffffffffu, old, 0);

    if (old == T_ - 1) {                   // this warp is the finisher for bk
        __threadfence();
        float s = (lane < T_) ? __ldcg(&g_partial[bk * 32 + lane]) : 0.0f;
        s += __shfl_xor_sync(0xffffffffu, s, 16);
        s += __shfl_xor_sync(0xffffffffu, s, 8);
        s += __shfl_xor_sync(0xffffffffu, s, 4);
        s += __shfl_xor_sync(0xffffffffu, s, 2);
        s += __shfl_xor_sync(0xffffffffu, s, 1);
        if (lane == 0) {
            out[bk] = s;
            g_cnt[bk] = 0;                 // reset for next graph replay
        }
    }
}

extern "C" void kernel_launch(void* const* d_in, const int* in_sizes, int n_in,
                              void* d_out, int out_size) {
    const float* preds = (const float*)d_in[0];
    const float* cn    = (const float*)d_in[1];
    const int*   mask  = (const int*)d_in[2];
    float* out = (float*)d_out;

    consistency_kernel<<<GRID, BLOCK>>>(preds, cn, mask, out);
}

// round 13
// speedup vs baseline: 1.3375x; 1.3375x over previous
#include <cuda_runtime.h>
#include <math.h>

// Problem constants (fixed by setup_inputs)
#define B_  32
#define K_  16
#define T_  30
#define N_  128
#define n_  20
#define NN  (N_ * n_)          // 2560 nodes per batch
#define BK  (B_ * K_)          // 512
#define BLOCK 256
#define CHUNK0 128             // phase-A nodes
#define REST   (NN - CHUNK0)   // 2432
#define NSEG   8
#define SEGLEN (REST / NSEG)   // 304

#define YAW_THRESH  1.0471975511965976f   // pi/3
#define INF_F       __int_as_float(0x7f800000)
#define INF_BITS    0x7f800000

__device__ __forceinline__ float fast_sqrt(float x) {
    float r;
    asm("sqrt.approx.f32 %0, %1;" : "=f"(r) : "f"(x));
    return r;
}

// cost = relu(dist - 2) + relu(|wrap(yaw_n - yaw_p)| - pi/3); masked -> inf.
// yaw = -atan2(dx, dy) reflects the direction angle, so |wrapped yaw diff| ==
// angle(u, v) between raw direction vectors (starts / t = 0 -> dir (0, 1)).
//
// KEY cheap-cost identities (tan(pi/3)^2 == 3):
//   angle <= pi/3  <=>  dt >= 0 AND cr^2 <= 3*dt^2   -> cost = relu(dist - 2)
//                                                        (NO transcendental)
//   otherwise cost >= relu(dist - 2) = cd            -> prune if cd >= lmin;
//                                                       atan2 only when a node
//                                                       could actually win.
// Exact zero: angle-ok AND d2 <= 4; cost >= 0 so any zero finalizes the min.
//
// One block per (b, k), 256 threads = 8 warps:
//  Phase 0: threads 0-127 build s_nd[128]; threads 128-157 build s_ptv[30].
//  Phase A: warp w handles t = w, w+8, w+16, w+24; nodes in registers.
//  Phase B: rare unresolved t's -> flattened (u, seg) items over 8 warps,
//           cheap-cost scan, atomicMin on int-encoded nonneg costs.
__global__ __launch_bounds__(BLOCK)
void consistency_kernel(const float* __restrict__ preds,
                        const float* __restrict__ cn,
                        const int*   __restrict__ mask,
                        float* __restrict__ out) {
    const int bk = blockIdx.x;
    const int b  = bk >> 4;                 // / K_

    const float2* cnb = (const float2*)cn + (size_t)b * NN;
    const int*    mb  = mask + (size_t)b * NN;
    const float2* pp  = (const float2*)preds + (size_t)bk * T_;

    __shared__ float4 s_nd[CHUNK0];         // 2 KB
    __shared__ float4 s_ptv[T_];
    __shared__ int    s_minb[32];
    __shared__ int    s_unres[32];
    __shared__ int    s_ucnt;

    const int tid  = threadIdx.x;
    const int warp = tid >> 5;
    const int lane = tid & 31;

    // ---------------- Phase 0 (split across warps) ----------------
    if (tid < CHUNK0) {
        const int idx = tid;
        float2 p = cnb[idx];
        float2 q = cnb[idx > 0 ? idx - 1 : 0];
        int    m = mb[idx];
        bool start = (idx % n_ == 0);
        float ux = start ? 0.0f : p.x - q.x;
        float uy = start ? 1.0f : p.y - q.y;
        float x  = (m == 1) ? INF_F : p.x;   // masked -> d2 = +inf
        s_nd[idx] = make_float4(x, p.y, ux, uy);
    } else if (tid < 128 + T_) {
        const int t = tid - 128;
        float2 pt = pp[t];
        float vx = 0.0f, vy = 1.0f;          // yaw 0 <-> direction (0, 1)
        if (t != 0) {
            float2 pm = pp[t - 1];
            vx = pt.x - pm.x;
            vy = pt.y - pm.y;
        }
        s_ptv[t] = make_float4(pt.x, pt.y, vx, vy);
    } else if (tid == 128 + T_) {
        s_ucnt = 0;
    } else if (tid >= 192 && tid < 224) {
        s_minb[tid - 192] = (tid - 192 < T_) ? INF_BITS : 0;
    }
    __syncthreads();

    // ---------------- Phase A: nodes in registers, 4 t's per warp ---------
    const float4 nd0 = s_nd[lane];
    const float4 nd1 = s_nd[lane + 32];
    const float4 nd2 = s_nd[lane + 64];
    const float4 nd3 = s_nd[lane + 96];

    #pragma unroll
    for (int i = 0; i < 4; ++i) {
        const int t = warp + i * 8;
        if (t >= T_) break;                  // warps 6,7 do 3 iterations
        const float4 ptv = s_ptv[t];

        float d2[4], dt[4], cr[4];
        bool  aok[4];                        // angle <= pi/3
        bool  anyz = false;

#define ZEVAL(j, ND) do {                                                  \
        float dx = (ND).x - ptv.x;                                         \
        float dy = (ND).y - ptv.y;                                         \
        d2[j] = fmaf(dx, dx, dy * dy);                                     \
        dt[j] = fmaf((ND).z, ptv.z, (ND).w * ptv.w);                       \
        cr[j] = fmaf((ND).z, ptv.w, -(ND).w * ptv.z);                      \
        aok[j] = (dt[j] >= 0.0f) && (cr[j] * cr[j] <= 3.0f * dt[j] * dt[j]);\
        anyz |= aok[j] && (d2[j] <= 4.0f);                                 \
    } while (0)

        ZEVAL(0, nd0);
        ZEVAL(1, nd1);
        ZEVAL(2, nd2);
        ZEVAL(3, nd3);
#undef ZEVAL

        if (__ballot_sync(0xffffffffu, anyz)) {
            if (lane == 0) s_minb[t] = 0;
        } else {
            // cheap costs: angle-ok -> cd; else atan2 only if cd < lmin
            float lmin = INF_F;
            #pragma unroll
            for (int j = 0; j < 4; ++j) {
                float cd = (d2[j] <= 4.0f) ? 0.0f : (fast_sqrt(d2[j]) - 2.0f);
                if (aok[j]) {
                    lmin = fminf(lmin, cd);
                } else if (cd < lmin) {
                    float a = atan2f(fabsf(cr[j]), dt[j]);
                    lmin = fminf(lmin, cd + fmaxf(a - YAW_THRESH, 0.0f));
                }
            }
            lmin = fminf(lmin, __shfl_xor_sync(0xffffffffu, lmin, 16));
            lmin = fminf(lmin, __shfl_xor_sync(0xffffffffu, lmin, 8));
            lmin = fminf(lmin, __shfl_xor_sync(0xffffffffu, lmin, 4));
            lmin = fminf(lmin, __shfl_xor_sync(0xffffffffu, lmin, 2));
            lmin = fminf(lmin, __shfl_xor_sync(0xffffffffu, lmin, 1));
            if (lane == 0) {
                s_minb[t] = __float_as_int(lmin);
                int pos = atomicAdd(&s_ucnt, 1);
                s_unres[pos] = t;
            }
        }
    }
    __syncthreads();

    // ---------------- Phase B: flattened straggler segments ---------------
    const int ucnt = s_ucnt;
    if (ucnt > 0) {
        const int nitems = ucnt * NSEG;
        for (int it = warp; it < nitems; it += 8) {
            const int u = it >> 3;
            const int s = it & (NSEG - 1);
            const int t = s_unres[u];
            const float4 ptv = s_ptv[t];

            const int segbase = CHUNK0 + s * SEGLEN;
            float lmin = __int_as_float(s_minb[t]);   // seed with known bound
            for (int off = lane; off < SEGLEN; off += 32) {
                const int idx = segbase + off;
                float2 p = cnb[idx];
                float2 q = cnb[idx - 1];
                int    m = mb[idx];
                bool start = (idx % n_ == 0);
                float ux = start ? 0.0f : p.x - q.x;
                float uy = start ? 1.0f : p.y - q.y;
                float x  = (m == 1) ? INF_F : p.x;

                float dx = x - ptv.x;
                float dy = p.y - ptv.y;
                float d2 = fmaf(dx, dx, dy * dy);
                float dt = fmaf(ux, ptv.z, uy * ptv.w);
                float cr = fmaf(ux, ptv.w, -uy * ptv.z);
                bool aok = (dt >= 0.0f) && (cr * cr <= 3.0f * dt * dt);

                float cd = (d2 <= 4.0f) ? 0.0f : (fast_sqrt(d2) - 2.0f);
                if (aok) {
                    lmin = fminf(lmin, cd);          // cost == cd exactly
                    if (lmin == 0.0f) break;         // global min reached
                } else if (cd < lmin) {              // prune: cost >= cd
                    float a = atan2f(fabsf(cr), dt);
                    lmin = fminf(lmin, cd + fmaxf(a - YAW_THRESH, 0.0f));
                }
            }
            lmin = fminf(lmin, __shfl_xor_sync(0xffffffffu, lmin, 16));
            lmin = fminf(lmin, __shfl_xor_sync(0xffffffffu, lmin, 8));
            lmin = fminf(lmin, __shfl_xor_sync(0xffffffffu, lmin, 4));
            lmin = fminf(lmin, __shfl_xor_sync(0xffffffffu, lmin, 2));
            lmin = fminf(lmin, __shfl_xor_sync(0xffffffffu, lmin, 1));
            // nonneg floats: int-bit order == value order -> deterministic
            if (lane == 0) atomicMin(&s_minb[t], __float_as_int(lmin));
        }
        __syncthreads();
    }

    // ---------------- Sum over T (deterministic shfl tree) ----------------
    if (tid < 32) {
        float v = __int_as_float(s_minb[tid]);   // t >= 30 slots hold 0
        v += __shfl_xor_sync(0xffffffffu, v, 16);
        v += __shfl_xor_sync(0xffffffffu, v, 8);
        v += __shfl_xor_sync(0xffffffffu, v, 4);
        v += __shfl_xor_sync(0xffffffffu, v, 2);
        v += __shfl_xor_sync(0xffffffffu, v, 1);
        if (tid == 0) out[bk] = v;
    }
}

extern "C" void kernel_launch(void* const* d_in, const int* in_sizes, int n_in,
                              void* d_out, int out_size) {
    const float* preds = (const float*)d_in[0];
    const float* cn    = (const float*)d_in[1];
    const int*   mask  = (const int*)d_in[2];
    float* out = (float*)d_out;

    consistency_kernel<<<BK, BLOCK>>>(preds, cn, mask, out);
}